// round 11
// baseline (speedup 1.0000x reference)
#include <cuda_runtime.h>
#include <cuda_fp16.h>

#define A_    96
#define DET0_ 256
#define T_    256
#define NZ_   32
#define NY_   256
#define NX_   256
#define DTH   0.0327249234748936795f   // pi/96
#define LAMB_ 0.01f

#define RX_   268                      // padded row length in cells
#define OFF_  4                        // zero-pad offset on every side
#define RROW_ 258                      // padded res row (u cells)
#define VOLN  (RX_ * RX_ * 32)         // halves per vol copy
#define VOLB  (VOLN * 2)               // bytes per vol copy
#define RES_U4 ((A_ * RROW_ * 32 * 2) / 16)   // res size in uint4 (99072)

// fp16 scratch. Vol pads NEVER written -> stay zero; res fully re-zeroed by
// pack every launch (fwd accumulates into it with atomics).
// copy 0: [y+OFF][x+OFF][z]  (x contiguous)   copy 1: [x+OFF][y+OFF][z]
__device__ __half g_vol_s[2 * VOLN];
__device__ __half g_res_h[A_ * RROW_ * 32];   // [a][(u+1)][z], 64 B cells

typedef unsigned long long ull;

__device__ __forceinline__ __half2 u2h(unsigned v) {
    return *reinterpret_cast<__half2*>(&v);
}
// acc(f32x2) += cvt_f32x2(h)
__device__ __forceinline__ void add2h(ull& acc, __half2 h) {
    float lo = __low2float(h), hi = __high2float(h);
    ull v; asm("mov.b64 %0, {%1, %2};" : "=l"(v) : "f"(lo), "f"(hi));
    asm("add.rn.f32x2 %0, %0, %1;" : "+l"(acc) : "l"(v));
}
__device__ __forceinline__ float2 unpack2(ull a) {
    float2 r; asm("mov.b64 {%0, %1}, %2;" : "=f"(r.x), "=f"(r.y) : "l"(a)); return r;
}
__device__ __forceinline__ __half2 lerp2(__half2 a, __half2 b, __half2 f) {
    return __hfma2(f, __hsub2(b, a), a);
}

__global__ void noop_kernel() {}

// ---------------------------------------------------------------------------
// Kernel 1: transpose+pack x -> fp16 vol cells (normal AND transposed copy),
// and zero the ENTIRE res buffer (fwd accumulates into it with atomics;
// 2048 blocks x 49 uint4 = 100352 >= 99072).
// ---------------------------------------------------------------------------
__global__ __launch_bounds__(256) void pack_kernel(const float* __restrict__ x) {
    {
        const int flat = blockIdx.y * 8 + blockIdx.x;
        const int idx = flat * 49 + threadIdx.x;
        if (threadIdx.x < 49 && idx < RES_U4)
            reinterpret_cast<uint4*>(g_res_h)[idx] = make_uint4(0u, 0u, 0u, 0u);
    }

    __shared__ float tile[32][33];   // [z][x]
    const int xb = blockIdx.x * 32;
    const int y  = blockIdx.y;
    {
        const int z  = threadIdx.x >> 3;
        const int xq = threadIdx.x & 7;
        float4 v = reinterpret_cast<const float4*>(x + z * (NY_ * NX_) + y * NX_ + xb)[xq];
        tile[z][4 * xq + 0] = v.x;
        tile[z][4 * xq + 1] = v.y;
        tile[z][4 * xq + 2] = v.z;
        tile[z][4 * xq + 3] = v.w;
    }
    __syncthreads();
    const int zo = threadIdx.x & 7;     // z quad: z = 4*zo..4*zo+3
    const int xl = threadIdx.x >> 3;    // 0..31
    __half2 h0 = __floats2half2_rn(tile[4 * zo + 0][xl], tile[4 * zo + 1][xl]);
    __half2 h1 = __floats2half2_rn(tile[4 * zo + 2][xl], tile[4 * zo + 3][xl]);
    uint2 w;
    w.x = *reinterpret_cast<unsigned*>(&h0);
    w.y = *reinterpret_cast<unsigned*>(&h1);
    const int xg = xb + xl;
    // normal copy [y][x][z]
    *reinterpret_cast<uint2*>(reinterpret_cast<char*>(g_vol_s)
        + ((y + OFF_) * RX_ + (xg + OFF_)) * 64 + zo * 8) = w;
    // transposed copy [x][y][z]
    *reinterpret_cast<uint2*>(reinterpret_cast<char*>(g_vol_s) + VOLB
        + ((xg + OFF_) * RX_ + (y + OFF_)) * 64 + zo * 8) = w;
}

// ---------------------------------------------------------------------------
// Kernel 2: forward project + residual. Grid (8, A, 2): blockIdx.z = t-seg.
// 128 thr: zo = tid&3 (uint4 = 8 z), ul = tid>>2 (32 u). Per-angle copy
// selection keeps u-adjacent warp footprints line-contiguous for ALL angles.
// Partials combined via fp16x2 atomicAdd (2 commutative adds -> determ.).
// ---------------------------------------------------------------------------
__global__ __launch_bounds__(128) void fwd_kernel(const float* __restrict__ p) {
    const int tid = threadIdx.x;
    const int zo  = tid & 3;
    const int ul  = tid >> 2;
    const int a   = blockIdx.y;
    const int u   = blockIdx.x * 32 + ul;
    const int seg = blockIdx.z;

    float s, c;
    sincosf((float)a * DTH, &s, &c);

    // u-step = (-s, c): mostly y for a<24 or a>=72 -> use transposed copy.
    const bool sw = (a < 24) || (a >= 72);
    const int SX = sw ? RX_ : 1;     // cell stride of +1 in x
    const int SY = sw ? 1 : RX_;     // cell stride of +1 in y
    const char* __restrict__ volb =
        reinterpret_cast<const char*>(g_vol_s) + (sw ? VOLB : 0);

    const float uc = (float)u - 127.5f;
    const float bx = fmaf(uc, -s, 127.5f);
    const float by = fmaf(uc,  c, 127.5f);

    // valid-t range via ray-box vs [-1,257]^2 (pads absorb float slop).
    const float xa = (-1.0f - bx) / c, xb2 = (257.0f - bx) / c;
    const float ya = (-1.0f - by) / s, yb2 = (257.0f - by) / s;
    const float lo = fmaxf(fminf(xa, xb2), fminf(ya, yb2));
    const float hi = fminf(fmaxf(xa, xb2), fmaxf(ya, yb2));
    int t0 = (int)fminf(fmaxf(lo + 126.0f, 0.0f), 256.0f);
    int t1 = (int)fminf(fmaxf(hi + 129.0f, -1.0f), 255.0f);
    t0 = max(t0, seg * 128);
    t1 = min(t1, seg * 128 + 127);

    ull acc0 = 0ull, acc1 = 0ull, acc2 = 0ull, acc3 = 0ull;

    float tf = (float)t0 - 127.5f;
    #pragma unroll 2
    for (int t = t0; t <= t1; ++t, tf += 1.0f) {
        const float ix = fmaf(tf, c, bx);
        const float iy = fmaf(tf, s, by);
        const float x0f = floorf(ix);
        const float y0f = floorf(iy);
        const float fx = ix - x0f;
        const float fy = iy - y0f;
        const int xi = (int)x0f + OFF_;
        const int yi = (int)y0f + OFF_;

        const char* cell = volb + (xi * SX + yi * SY) * 64 + zo * 16;
        const uint4 L0 = *reinterpret_cast<const uint4*>(cell);
        const uint4 R0 = *reinterpret_cast<const uint4*>(cell + SX * 64);
        const uint4 L1 = *reinterpret_cast<const uint4*>(cell + SY * 64);
        const uint4 R1 = *reinterpret_cast<const uint4*>(cell + (SX + SY) * 64);

        const __half2 fxh = __float2half2_rn(fx);
        const __half2 fyh = __float2half2_rn(fy);

        const __half2 s0 = lerp2(lerp2(u2h(L0.x), u2h(R0.x), fxh),
                                 lerp2(u2h(L1.x), u2h(R1.x), fxh), fyh);
        const __half2 s1 = lerp2(lerp2(u2h(L0.y), u2h(R0.y), fxh),
                                 lerp2(u2h(L1.y), u2h(R1.y), fxh), fyh);
        const __half2 s2 = lerp2(lerp2(u2h(L0.z), u2h(R0.z), fxh),
                                 lerp2(u2h(L1.z), u2h(R1.z), fxh), fyh);
        const __half2 s3 = lerp2(lerp2(u2h(L0.w), u2h(R0.w), fxh),
                                 lerp2(u2h(L1.w), u2h(R1.w), fxh), fyh);

        add2h(acc0, s0);
        add2h(acc1, s1);
        add2h(acc2, s2);
        add2h(acc3, s3);
    }

    const float2 f0 = unpack2(acc0);
    const float2 f1 = unpack2(acc1);
    const float2 f2 = unpack2(acc2);
    const float2 f3 = unpack2(acc3);
    float r[8] = {f0.x, f0.y, f1.x, f1.y, f2.x, f2.y, f3.x, f3.y};

    if (seg == 0) {
        #pragma unroll
        for (int e = 0; e < 8; ++e) {
            // z = 8*zo + e; m = (e<<2) | zo
            const int m = (e << 2) | zo;
            r[e] -= p[(a * 4 + (m >> 3)) * (8 * 256) + (m & 7) * 256 + u];
        }
    }

    __half2* dst = reinterpret_cast<__half2*>(
        g_res_h + (a * RROW_ + u + 1) * 32 + zo * 8);
    atomicAdd(dst + 0, __floats2half2_rn(r[0], r[1]));
    atomicAdd(dst + 1, __floats2half2_rn(r[2], r[3]));
    atomicAdd(dst + 2, __floats2half2_rn(r[4], r[5]));
    atomicAdd(dst + 3, __floats2half2_rn(r[6], r[7]));
}

// ---------------------------------------------------------------------------
// Kernel 3: back project. Block = 16x4 pixels x 4 zo, 256 thr.
// Branchless validity (invalid -> pad cell with weight 0); angles paired,
// per-pair fp16 combine then one f32x2 accumulate.
// ---------------------------------------------------------------------------
__global__ __launch_bounds__(256) void bwd_kernel(float* __restrict__ out) {
    __shared__ float2 ang[A_];
    const int tid = threadIdx.x;
    if (tid < A_) {
        float s, c;
        sincosf((float)tid * DTH, &s, &c);
        ang[tid] = make_float2(s, c);
    }
    __syncthreads();

    const int zo   = tid & 3;
    const int slot = tid >> 2;     // 0..63
    const int sx   = slot & 15;
    const int sy   = slot >> 4;    // 0..3
    const int x = blockIdx.x * 16 + sx;
    const int y = blockIdx.y * 4 + sy;

    const float Xc = (float)x - 127.5f;
    const float Yc = (float)y - 127.5f;

    ull acc0 = 0ull, acc1 = 0ull, acc2 = 0ull, acc3 = 0ull;
    const char* __restrict__ resb = reinterpret_cast<const char*>(g_res_h);

    #pragma unroll 2
    for (int a = 0; a < A_; a += 2) {
        const float2 an0 = ang[a];
        const float2 an1 = ang[a + 1];

        const float ub0 = fmaf(Yc, an0.y, fmaf(Xc, -an0.x, 127.5f));
        const float ub1 = fmaf(Yc, an1.y, fmaf(Xc, -an1.x, 127.5f));
        int u0 = __float2int_rd(ub0);
        int u1 = __float2int_rd(ub1);
        const bool v0 = (unsigned)(u0 + 1) <= 256u;
        const bool v1 = (unsigned)(u1 + 1) <= 256u;
        const float fu0 = v0 ? (ub0 - (float)u0) : 0.0f;
        const float fu1 = v1 ? (ub1 - (float)u1) : 0.0f;
        u0 = v0 ? u0 : -1;   // pad cell (zero), weight 0 on the live tap
        u1 = v1 ? u1 : -1;

        const char* c0 = resb + (a * RROW_ + u0 + 1) * 64 + zo * 16;
        const char* c1 = resb + ((a + 1) * RROW_ + u1 + 1) * 64 + zo * 16;
        const uint4 q00 = *reinterpret_cast<const uint4*>(c0);
        const uint4 q01 = *reinterpret_cast<const uint4*>(c0 + 64);
        const uint4 q10 = *reinterpret_cast<const uint4*>(c1);
        const uint4 q11 = *reinterpret_cast<const uint4*>(c1 + 64);

        const __half2 f0h = __float2half2_rn(fu0);
        const __half2 f1h = __float2half2_rn(fu1);

        add2h(acc0, __hadd2(lerp2(u2h(q00.x), u2h(q01.x), f0h),
                            lerp2(u2h(q10.x), u2h(q11.x), f1h)));
        add2h(acc1, __hadd2(lerp2(u2h(q00.y), u2h(q01.y), f0h),
                            lerp2(u2h(q10.y), u2h(q11.y), f1h)));
        add2h(acc2, __hadd2(lerp2(u2h(q00.z), u2h(q01.z), f0h),
                            lerp2(u2h(q10.z), u2h(q11.z), f1h)));
        add2h(acc3, __hadd2(lerp2(u2h(q00.w), u2h(q01.w), f0h),
                            lerp2(u2h(q10.w), u2h(q11.w), f1h)));
    }

    const float2 f0 = unpack2(acc0);
    const float2 f1 = unpack2(acc1);
    const float2 f2 = unpack2(acc2);
    const float2 f3 = unpack2(acc3);
    const float vals[8] = {f0.x, f0.y, f1.x, f1.y, f2.x, f2.y, f3.x, f3.y};

    const float L = -LAMB_;
    const int base = y * NX_ + x;
    #pragma unroll
    for (int e = 0; e < 8; ++e)
        out[(8 * zo + e) * (NY_ * NX_) + base] = L * vals[e];
}

// ---------------------------------------------------------------------------
extern "C" void kernel_launch(void* const* d_in, const int* in_sizes, int n_in,
                              void* d_out, int out_size) {
    const float* x = (const float*)d_in[0];
    const float* p = (const float*)d_in[1];
    if (n_in >= 2 && in_sizes[0] == 786432) {   // defensive swap by size
        const float* tmp = x; x = p; p = tmp;
    }
    float* out = (float*)d_out;

    // Two no-ops keep the ncu capture point (-s 5) on fwd_kernel.
    noop_kernel<<<1, 32>>>();
    noop_kernel<<<1, 32>>>();
    pack_kernel<<<dim3(NX_ / 32, NY_), 256>>>(x);
    fwd_kernel<<<dim3(DET0_ / 32, A_, 2), 128>>>(p);
    bwd_kernel<<<dim3(NX_ / 16, NY_ / 4), 256>>>(out);
}

// round 12
// speedup vs baseline: 1.0002x; 1.0002x over previous
#include <cuda_runtime.h>
#include <cuda_fp16.h>

#define A_    96
#define DET0_ 256
#define T_    256
#define NZ_   32
#define NY_   256
#define NX_   256
#define DTH   0.0327249234748936795f   // pi/96
#define LAMB_ 0.01f

#define RX_   268                      // padded row length in cells
#define OFF_  4                        // zero-pad offset on every side
#define RROW_ 258                      // padded res row (u cells)
#define VOLN  (RX_ * RX_ * 32)         // halves per vol copy
#define VOLB  (VOLN * 2)               // bytes per vol copy
#define RES_U4 ((A_ * RROW_ * 32 * 2) / 16)   // res size in uint4 (99072)

// fp16 scratch. Vol pads NEVER written -> stay zero; res fully re-zeroed by
// pack every launch (fwd accumulates into it with atomics).
// copy 0: [y+OFF][x+OFF][z]  (x contiguous)   copy 1: [x+OFF][y+OFF][z]
__device__ __half g_vol_s[2 * VOLN];
__device__ __half g_res_h[A_ * RROW_ * 32];   // [a][(u+1)][z], 64 B cells

typedef unsigned long long ull;

__device__ __forceinline__ __half2 u2h(unsigned v) {
    return *reinterpret_cast<__half2*>(&v);
}
// acc(f32x2) += cvt_f32x2(h)
__device__ __forceinline__ void add2h(ull& acc, __half2 h) {
    float lo = __low2float(h), hi = __high2float(h);
    ull v; asm("mov.b64 %0, {%1, %2};" : "=l"(v) : "f"(lo), "f"(hi));
    asm("add.rn.f32x2 %0, %0, %1;" : "+l"(acc) : "l"(v));
}
__device__ __forceinline__ float2 unpack2(ull a) {
    float2 r; asm("mov.b64 {%0, %1}, %2;" : "=f"(r.x), "=f"(r.y) : "l"(a)); return r;
}
__device__ __forceinline__ __half2 lerp2(__half2 a, __half2 b, __half2 f) {
    return __hfma2(f, __hsub2(b, a), a);
}

__global__ void noop_kernel() {}

// ---------------------------------------------------------------------------
// Kernel 1: transpose+pack x -> fp16 vol cells (normal AND transposed copy),
// and zero the ENTIRE res buffer (2048 blocks x 49 uint4 = 100352 >= 99072).
// ---------------------------------------------------------------------------
__global__ __launch_bounds__(256) void pack_kernel(const float* __restrict__ x) {
    {
        const int flat = blockIdx.y * 8 + blockIdx.x;
        const int idx = flat * 49 + threadIdx.x;
        if (threadIdx.x < 49 && idx < RES_U4)
            reinterpret_cast<uint4*>(g_res_h)[idx] = make_uint4(0u, 0u, 0u, 0u);
    }

    __shared__ float tile[32][33];   // [z][x]
    const int xb = blockIdx.x * 32;
    const int y  = blockIdx.y;
    {
        const int z  = threadIdx.x >> 3;
        const int xq = threadIdx.x & 7;
        float4 v = reinterpret_cast<const float4*>(x + z * (NY_ * NX_) + y * NX_ + xb)[xq];
        tile[z][4 * xq + 0] = v.x;
        tile[z][4 * xq + 1] = v.y;
        tile[z][4 * xq + 2] = v.z;
        tile[z][4 * xq + 3] = v.w;
    }
    __syncthreads();
    const int zo = threadIdx.x & 7;     // z quad: z = 4*zo..4*zo+3
    const int xl = threadIdx.x >> 3;    // 0..31
    __half2 h0 = __floats2half2_rn(tile[4 * zo + 0][xl], tile[4 * zo + 1][xl]);
    __half2 h1 = __floats2half2_rn(tile[4 * zo + 2][xl], tile[4 * zo + 3][xl]);
    uint2 w;
    w.x = *reinterpret_cast<unsigned*>(&h0);
    w.y = *reinterpret_cast<unsigned*>(&h1);
    const int xg = xb + xl;
    // normal copy [y][x][z]
    *reinterpret_cast<uint2*>(reinterpret_cast<char*>(g_vol_s)
        + ((y + OFF_) * RX_ + (xg + OFF_)) * 64 + zo * 8) = w;
    // transposed copy [x][y][z]
    *reinterpret_cast<uint2*>(reinterpret_cast<char*>(g_vol_s) + VOLB
        + ((xg + OFF_) * RX_ + (y + OFF_)) * 64 + zo * 8) = w;
}

// ---------------------------------------------------------------------------
// Kernel 2: forward project + residual. Grid (8, A, 2): blockIdx.z = t-seg.
// 128 thr: zo = tid&3 (uint4 = 8 z), ul = tid>>2 (32 u).
// For angles where the u-direction is mostly y (a<24 or a>=72), trace the ray
// in SWAPPED coordinates against the transposed copy -> u-adjacent lanes are
// line-contiguous for ALL angles, with compile-time strides (no per-step ALU).
// Partials combined via fp16x2 atomicAdd (2 commutative adds -> determ.).
// ---------------------------------------------------------------------------
__global__ __launch_bounds__(128) void fwd_kernel(const float* __restrict__ p) {
    const int tid = threadIdx.x;
    const int zo  = tid & 3;
    const int ul  = tid >> 2;
    const int a   = blockIdx.y;
    const int u   = blockIdx.x * 32 + ul;
    const int seg = blockIdx.z;

    float s, c;
    sincosf((float)a * DTH, &s, &c);

    const float uc = (float)u - 127.5f;
    float cc = c, ss = s;
    float bxx = fmaf(uc, -s, 127.5f);
    float byy = fmaf(uc,  c, 127.5f);

    // u-step = (-s, c): mostly y for a<24 or a>=72 -> swap coords, use
    // transposed copy. Box is x/y-symmetric so range code below is unchanged.
    const bool sw = (a < 24) || (a >= 72);
    const char* __restrict__ volb =
        reinterpret_cast<const char*>(g_vol_s) + (sw ? VOLB : 0);
    if (sw) {
        float t0v = cc; cc = ss; ss = t0v;
        float t1v = bxx; bxx = byy; byy = t1v;
    }

    // valid-t range via ray-box vs [-1,257]^2 (pads absorb float slop).
    const float xa = (-1.0f - bxx) / cc, xb2 = (257.0f - bxx) / cc;
    const float ya = (-1.0f - byy) / ss, yb2 = (257.0f - byy) / ss;
    const float lo = fmaxf(fminf(xa, xb2), fminf(ya, yb2));
    const float hi = fminf(fmaxf(xa, xb2), fmaxf(ya, yb2));
    int t0 = (int)fminf(fmaxf(lo + 126.0f, 0.0f), 256.0f);
    int t1 = (int)fminf(fmaxf(hi + 129.0f, -1.0f), 255.0f);
    t0 = max(t0, seg * 128);
    t1 = min(t1, seg * 128 + 127);

    ull acc0 = 0ull, acc1 = 0ull, acc2 = 0ull, acc3 = 0ull;

    float tf = (float)t0 - 127.5f;
    #pragma unroll 2
    for (int t = t0; t <= t1; ++t, tf += 1.0f) {
        const float ix = fmaf(tf, cc, bxx);
        const float iy = fmaf(tf, ss, byy);
        const float x0f = floorf(ix);
        const float y0f = floorf(iy);
        const float fx = ix - x0f;
        const float fy = iy - y0f;
        const int xi = (int)x0f + OFF_;
        const int yi = (int)y0f + OFF_;

        const char* cell = volb + (yi * RX_ + xi) * 64 + zo * 16;
        const uint4 L0 = *reinterpret_cast<const uint4*>(cell);
        const uint4 R0 = *reinterpret_cast<const uint4*>(cell + 64);
        const uint4 L1 = *reinterpret_cast<const uint4*>(cell + RX_ * 64);
        const uint4 R1 = *reinterpret_cast<const uint4*>(cell + RX_ * 64 + 64);

        const __half2 fxh = __float2half2_rn(fx);
        const __half2 fyh = __float2half2_rn(fy);

        const __half2 s0 = lerp2(lerp2(u2h(L0.x), u2h(R0.x), fxh),
                                 lerp2(u2h(L1.x), u2h(R1.x), fxh), fyh);
        const __half2 s1 = lerp2(lerp2(u2h(L0.y), u2h(R0.y), fxh),
                                 lerp2(u2h(L1.y), u2h(R1.y), fxh), fyh);
        const __half2 s2 = lerp2(lerp2(u2h(L0.z), u2h(R0.z), fxh),
                                 lerp2(u2h(L1.z), u2h(R1.z), fxh), fyh);
        const __half2 s3 = lerp2(lerp2(u2h(L0.w), u2h(R0.w), fxh),
                                 lerp2(u2h(L1.w), u2h(R1.w), fxh), fyh);

        add2h(acc0, s0);
        add2h(acc1, s1);
        add2h(acc2, s2);
        add2h(acc3, s3);
    }

    const float2 f0 = unpack2(acc0);
    const float2 f1 = unpack2(acc1);
    const float2 f2 = unpack2(acc2);
    const float2 f3 = unpack2(acc3);
    float r[8] = {f0.x, f0.y, f1.x, f1.y, f2.x, f2.y, f3.x, f3.y};

    if (seg == 0) {
        #pragma unroll
        for (int e = 0; e < 8; ++e) {
            // z = 8*zo + e; m = (e<<2) | zo
            const int m = (e << 2) | zo;
            r[e] -= p[(a * 4 + (m >> 3)) * (8 * 256) + (m & 7) * 256 + u];
        }
    }

    __half2* dst = reinterpret_cast<__half2*>(
        g_res_h + (a * RROW_ + u + 1) * 32 + zo * 8);
    atomicAdd(dst + 0, __floats2half2_rn(r[0], r[1]));
    atomicAdd(dst + 1, __floats2half2_rn(r[2], r[3]));
    atomicAdd(dst + 2, __floats2half2_rn(r[4], r[5]));
    atomicAdd(dst + 3, __floats2half2_rn(r[6], r[7]));
}

// ---------------------------------------------------------------------------
// Kernel 3: back project. Block = 16x4 pixels x 4 zo, 256 thr.
// Branchless validity (invalid -> pad cell with weight 0); angles paired,
// per-pair fp16 combine then one f32x2 accumulate.
// ---------------------------------------------------------------------------
__global__ __launch_bounds__(256) void bwd_kernel(float* __restrict__ out) {
    __shared__ float2 ang[A_];
    const int tid = threadIdx.x;
    if (tid < A_) {
        float s, c;
        sincosf((float)tid * DTH, &s, &c);
        ang[tid] = make_float2(s, c);
    }
    __syncthreads();

    const int zo   = tid & 3;
    const int slot = tid >> 2;     // 0..63
    const int sx   = slot & 15;
    const int sy   = slot >> 4;    // 0..3
    const int x = blockIdx.x * 16 + sx;
    const int y = blockIdx.y * 4 + sy;

    const float Xc = (float)x - 127.5f;
    const float Yc = (float)y - 127.5f;

    ull acc0 = 0ull, acc1 = 0ull, acc2 = 0ull, acc3 = 0ull;
    const char* __restrict__ resb = reinterpret_cast<const char*>(g_res_h);

    #pragma unroll 2
    for (int a = 0; a < A_; a += 2) {
        const float2 an0 = ang[a];
        const float2 an1 = ang[a + 1];

        const float ub0 = fmaf(Yc, an0.y, fmaf(Xc, -an0.x, 127.5f));
        const float ub1 = fmaf(Yc, an1.y, fmaf(Xc, -an1.x, 127.5f));
        int u0 = __float2int_rd(ub0);
        int u1 = __float2int_rd(ub1);
        const bool v0 = (unsigned)(u0 + 1) <= 256u;
        const bool v1 = (unsigned)(u1 + 1) <= 256u;
        const float fu0 = v0 ? (ub0 - (float)u0) : 0.0f;
        const float fu1 = v1 ? (ub1 - (float)u1) : 0.0f;
        u0 = v0 ? u0 : -1;   // pad cell (zero), weight 0 on the live tap
        u1 = v1 ? u1 : -1;

        const char* c0 = resb + (a * RROW_ + u0 + 1) * 64 + zo * 16;
        const char* c1 = resb + ((a + 1) * RROW_ + u1 + 1) * 64 + zo * 16;
        const uint4 q00 = *reinterpret_cast<const uint4*>(c0);
        const uint4 q01 = *reinterpret_cast<const uint4*>(c0 + 64);
        const uint4 q10 = *reinterpret_cast<const uint4*>(c1);
        const uint4 q11 = *reinterpret_cast<const uint4*>(c1 + 64);

        const __half2 f0h = __float2half2_rn(fu0);
        const __half2 f1h = __float2half2_rn(fu1);

        add2h(acc0, __hadd2(lerp2(u2h(q00.x), u2h(q01.x), f0h),
                            lerp2(u2h(q10.x), u2h(q11.x), f1h)));
        add2h(acc1, __hadd2(lerp2(u2h(q00.y), u2h(q01.y), f0h),
                            lerp2(u2h(q10.y), u2h(q11.y), f1h)));
        add2h(acc2, __hadd2(lerp2(u2h(q00.z), u2h(q01.z), f0h),
                            lerp2(u2h(q10.z), u2h(q11.z), f1h)));
        add2h(acc3, __hadd2(lerp2(u2h(q00.w), u2h(q01.w), f0h),
                            lerp2(u2h(q10.w), u2h(q11.w), f1h)));
    }

    const float2 f0 = unpack2(acc0);
    const float2 f1 = unpack2(acc1);
    const float2 f2 = unpack2(acc2);
    const float2 f3 = unpack2(acc3);
    const float vals[8] = {f0.x, f0.y, f1.x, f1.y, f2.x, f2.y, f3.x, f3.y};

    const float L = -LAMB_;
    const int base = y * NX_ + x;
    #pragma unroll
    for (int e = 0; e < 8; ++e)
        out[(8 * zo + e) * (NY_ * NX_) + base] = L * vals[e];
}

// ---------------------------------------------------------------------------
extern "C" void kernel_launch(void* const* d_in, const int* in_sizes, int n_in,
                              void* d_out, int out_size) {
    const float* x = (const float*)d_in[0];
    const float* p = (const float*)d_in[1];
    if (n_in >= 2 && in_sizes[0] == 786432) {   // defensive swap by size
        const float* tmp = x; x = p; p = tmp;
    }
    float* out = (float*)d_out;

    // Two no-ops keep the ncu capture point (-s 5) on fwd_kernel.
    noop_kernel<<<1, 32>>>();
    noop_kernel<<<1, 32>>>();
    pack_kernel<<<dim3(NX_ / 32, NY_), 256>>>(x);
    fwd_kernel<<<dim3(DET0_ / 32, A_, 2), 128>>>(p);
    bwd_kernel<<<dim3(NX_ / 16, NY_ / 4), 256>>>(out);
}

// round 13
// speedup vs baseline: 1.0447x; 1.0445x over previous
#include <cuda_runtime.h>
#include <cuda_fp16.h>

#define A_    96
#define DET0_ 256
#define T_    256
#define NZ_   32
#define NY_   256
#define NX_   256
#define DTH   0.0327249234748936795f   // pi/96
#define LAMB_ 0.01f

#define RX_   268                      // padded row length in cells
#define OFF_  4                        // zero-pad offset on every side
#define RROW_ 258                      // padded res row (u cells)
#define RES_U4 ((A_ * RROW_ * 32 * 2) / 16)   // res size in uint4 (99072)

// fp16 scratch. Vol pads NEVER written -> stay zero; res fully re-zeroed by
// pack every launch (fwd accumulates into it with atomics).
__device__ __half g_vol_s[RX_ * RX_ * 32];    // [y+OFF][x+OFF][z], 64 B cells
__device__ __half g_res_h[A_ * RROW_ * 32];   // [a][(u+1)][z], 64 B cells

typedef unsigned long long ull;

__device__ __forceinline__ __half2 u2h(unsigned v) {
    return *reinterpret_cast<__half2*>(&v);
}
// acc(f32x2) += cvt_f32x2(h)
__device__ __forceinline__ void add2h(ull& acc, __half2 h) {
    float lo = __low2float(h), hi = __high2float(h);
    ull v; asm("mov.b64 %0, {%1, %2};" : "=l"(v) : "f"(lo), "f"(hi));
    asm("add.rn.f32x2 %0, %0, %1;" : "+l"(acc) : "l"(v));
}
__device__ __forceinline__ float2 unpack2(ull a) {
    float2 r; asm("mov.b64 {%0, %1}, %2;" : "=f"(r.x), "=f"(r.y) : "l"(a)); return r;
}
__device__ __forceinline__ __half2 lerp2(__half2 a, __half2 b, __half2 f) {
    return __hfma2(f, __hsub2(b, a), a);
}

struct S4 { __half2 a, b, c, d; };

// One bilinear sample (8 z as 4 half2), fully fp16 lerp.
__device__ __forceinline__ S4 sample_at(const char* __restrict__ volb,
                                        float tf, float cc, float ss,
                                        float bxx, float byy, int zo) {
    const float ix = fmaf(tf, cc, bxx);
    const float iy = fmaf(tf, ss, byy);
    const float x0f = floorf(ix);
    const float y0f = floorf(iy);
    const float fx = ix - x0f;
    const float fy = iy - y0f;
    const int xi = (int)x0f + OFF_;
    const int yi = (int)y0f + OFF_;

    const char* cell = volb + (yi * RX_ + xi) * 64 + zo * 16;
    const uint4 L0 = *reinterpret_cast<const uint4*>(cell);
    const uint4 R0 = *reinterpret_cast<const uint4*>(cell + 64);
    const uint4 L1 = *reinterpret_cast<const uint4*>(cell + RX_ * 64);
    const uint4 R1 = *reinterpret_cast<const uint4*>(cell + RX_ * 64 + 64);

    const __half2 fxh = __float2half2_rn(fx);
    const __half2 fyh = __float2half2_rn(fy);

    S4 r;
    r.a = lerp2(lerp2(u2h(L0.x), u2h(R0.x), fxh),
                lerp2(u2h(L1.x), u2h(R1.x), fxh), fyh);
    r.b = lerp2(lerp2(u2h(L0.y), u2h(R0.y), fxh),
                lerp2(u2h(L1.y), u2h(R1.y), fxh), fyh);
    r.c = lerp2(lerp2(u2h(L0.z), u2h(R0.z), fxh),
                lerp2(u2h(L1.z), u2h(R1.z), fxh), fyh);
    r.d = lerp2(lerp2(u2h(L0.w), u2h(R0.w), fxh),
                lerp2(u2h(L1.w), u2h(R1.w), fxh), fyh);
    return r;
}

__global__ void noop_kernel() {}

// ---------------------------------------------------------------------------
// Kernel 1: transpose+pack x -> fp16 vol cells, and zero the ENTIRE res
// buffer (2048 blocks x 49 uint4 = 100352 >= 99072).
// ---------------------------------------------------------------------------
__global__ __launch_bounds__(256) void pack_kernel(const float* __restrict__ x) {
    {
        const int flat = blockIdx.y * 8 + blockIdx.x;
        const int idx = flat * 49 + threadIdx.x;
        if (threadIdx.x < 49 && idx < RES_U4)
            reinterpret_cast<uint4*>(g_res_h)[idx] = make_uint4(0u, 0u, 0u, 0u);
    }

    __shared__ float tile[32][33];   // [z][x]
    const int xb = blockIdx.x * 32;
    const int y  = blockIdx.y;
    {
        const int z  = threadIdx.x >> 3;
        const int xq = threadIdx.x & 7;
        float4 v = reinterpret_cast<const float4*>(x + z * (NY_ * NX_) + y * NX_ + xb)[xq];
        tile[z][4 * xq + 0] = v.x;
        tile[z][4 * xq + 1] = v.y;
        tile[z][4 * xq + 2] = v.z;
        tile[z][4 * xq + 3] = v.w;
    }
    __syncthreads();
    const int zo = threadIdx.x & 7;     // z quad: z = 4*zo..4*zo+3
    const int xl = threadIdx.x >> 3;    // 0..31
    __half2 h0 = __floats2half2_rn(tile[4 * zo + 0][xl], tile[4 * zo + 1][xl]);
    __half2 h1 = __floats2half2_rn(tile[4 * zo + 2][xl], tile[4 * zo + 3][xl]);
    uint2 w;
    w.x = *reinterpret_cast<unsigned*>(&h0);
    w.y = *reinterpret_cast<unsigned*>(&h1);
    *reinterpret_cast<uint2*>(reinterpret_cast<char*>(g_vol_s)
        + ((y + OFF_) * RX_ + (xb + xl + OFF_)) * 64 + zo * 8) = w;
}

// ---------------------------------------------------------------------------
// Kernel 2: forward project + residual. Grid (8, A, 2): blockIdx.z selects
// the PER-RAY half (midpoint split -> both blocks of a ray do equal work).
// 128 thr: zo = tid&3 (uint4 = 8 z), ul = tid>>2 (32 u). Consecutive t pairs
// combined in fp16 before one f32x2 accumulate. Partials via fp16x2
// atomicAdd (exactly 2 commutative adds per address -> deterministic).
// ---------------------------------------------------------------------------
__global__ __launch_bounds__(128) void fwd_kernel(const float* __restrict__ p) {
    const int tid = threadIdx.x;
    const int zo  = tid & 3;
    const int ul  = tid >> 2;
    const int a   = blockIdx.y;
    const int u   = blockIdx.x * 32 + ul;
    const int seg = blockIdx.z;

    float s, c;
    sincosf((float)a * DTH, &s, &c);

    const float uc = (float)u - 127.5f;
    const float bxx = fmaf(uc, -s, 127.5f);
    const float byy = fmaf(uc,  c, 127.5f);

    // valid-t range via ray-box vs [-1,257]^2 (pads absorb float slop).
    const float xa = (-1.0f - bxx) / c, xb2 = (257.0f - bxx) / c;
    const float ya = (-1.0f - byy) / s, yb2 = (257.0f - byy) / s;
    const float lo = fmaxf(fminf(xa, xb2), fminf(ya, yb2));
    const float hi = fminf(fmaxf(xa, xb2), fmaxf(ya, yb2));
    const int t0g = (int)fminf(fmaxf(lo + 126.0f, 0.0f), 256.0f);
    const int t1g = (int)fminf(fmaxf(hi + 129.0f, -1.0f), 255.0f);
    // per-ray midpoint split: seg0 = [t0g, mid), seg1 = [mid, t1g]
    const int mid = (t0g + t1g + 1) >> 1;
    const int t0 = seg ? mid : t0g;
    const int t1 = seg ? t1g : (mid - 1);

    ull acc0 = 0ull, acc1 = 0ull, acc2 = 0ull, acc3 = 0ull;
    const char* __restrict__ volb = reinterpret_cast<const char*>(g_vol_s);

    const int len = t1 - t0 + 1;
    const int nPairs = (len > 0) ? (len >> 1) : 0;

    float tf = (float)t0 - 127.5f;
    for (int i = 0; i < nPairs; ++i, tf += 2.0f) {
        const S4 sA = sample_at(volb, tf,        c, s, bxx, byy, zo);
        const S4 sB = sample_at(volb, tf + 1.0f, c, s, bxx, byy, zo);
        add2h(acc0, __hadd2(sA.a, sB.a));
        add2h(acc1, __hadd2(sA.b, sB.b));
        add2h(acc2, __hadd2(sA.c, sB.c));
        add2h(acc3, __hadd2(sA.d, sB.d));
    }
    if (len > 0 && (len & 1)) {
        const S4 sA = sample_at(volb, tf, c, s, bxx, byy, zo);
        add2h(acc0, sA.a);
        add2h(acc1, sA.b);
        add2h(acc2, sA.c);
        add2h(acc3, sA.d);
    }

    const float2 f0 = unpack2(acc0);
    const float2 f1 = unpack2(acc1);
    const float2 f2 = unpack2(acc2);
    const float2 f3 = unpack2(acc3);
    float r[8] = {f0.x, f0.y, f1.x, f1.y, f2.x, f2.y, f3.x, f3.y};

    if (seg == 0) {
        #pragma unroll
        for (int e = 0; e < 8; ++e) {
            // z = 8*zo + e; m = (e<<2) | zo
            const int m = (e << 2) | zo;
            r[e] -= p[(a * 4 + (m >> 3)) * (8 * 256) + (m & 7) * 256 + u];
        }
    }

    __half2* dst = reinterpret_cast<__half2*>(
        g_res_h + (a * RROW_ + u + 1) * 32 + zo * 8);
    atomicAdd(dst + 0, __floats2half2_rn(r[0], r[1]));
    atomicAdd(dst + 1, __floats2half2_rn(r[2], r[3]));
    atomicAdd(dst + 2, __floats2half2_rn(r[4], r[5]));
    atomicAdd(dst + 3, __floats2half2_rn(r[6], r[7]));
}

// ---------------------------------------------------------------------------
// Kernel 3: back project. Block = 16x4 pixels x 4 zo, 256 thr.
// Branchless validity (invalid -> pad cell, weight 0); angles paired,
// per-pair fp16 combine then one f32x2 accumulate.
// ---------------------------------------------------------------------------
__global__ __launch_bounds__(256) void bwd_kernel(float* __restrict__ out) {
    __shared__ float2 ang[A_];
    const int tid = threadIdx.x;
    if (tid < A_) {
        float s, c;
        sincosf((float)tid * DTH, &s, &c);
        ang[tid] = make_float2(s, c);
    }
    __syncthreads();

    const int zo   = tid & 3;
    const int slot = tid >> 2;     // 0..63
    const int sx   = slot & 15;
    const int sy   = slot >> 4;    // 0..3
    const int x = blockIdx.x * 16 + sx;
    const int y = blockIdx.y * 4 + sy;

    const float Xc = (float)x - 127.5f;
    const float Yc = (float)y - 127.5f;

    ull acc0 = 0ull, acc1 = 0ull, acc2 = 0ull, acc3 = 0ull;
    const char* __restrict__ resb = reinterpret_cast<const char*>(g_res_h);

    #pragma unroll 2
    for (int a = 0; a < A_; a += 2) {
        const float2 an0 = ang[a];
        const float2 an1 = ang[a + 1];

        const float ub0 = fmaf(Yc, an0.y, fmaf(Xc, -an0.x, 127.5f));
        const float ub1 = fmaf(Yc, an1.y, fmaf(Xc, -an1.x, 127.5f));
        int u0 = __float2int_rd(ub0);
        int u1 = __float2int_rd(ub1);
        const bool v0 = (unsigned)(u0 + 1) <= 256u;
        const bool v1 = (unsigned)(u1 + 1) <= 256u;
        const float fu0 = v0 ? (ub0 - (float)u0) : 0.0f;
        const float fu1 = v1 ? (ub1 - (float)u1) : 0.0f;
        u0 = v0 ? u0 : -1;   // pad cell (zero), weight 0 on the live tap
        u1 = v1 ? u1 : -1;

        const char* c0 = resb + (a * RROW_ + u0 + 1) * 64 + zo * 16;
        const char* c1 = resb + ((a + 1) * RROW_ + u1 + 1) * 64 + zo * 16;
        const uint4 q00 = *reinterpret_cast<const uint4*>(c0);
        const uint4 q01 = *reinterpret_cast<const uint4*>(c0 + 64);
        const uint4 q10 = *reinterpret_cast<const uint4*>(c1);
        const uint4 q11 = *reinterpret_cast<const uint4*>(c1 + 64);

        const __half2 f0h = __float2half2_rn(fu0);
        const __half2 f1h = __float2half2_rn(fu1);

        add2h(acc0, __hadd2(lerp2(u2h(q00.x), u2h(q01.x), f0h),
                            lerp2(u2h(q10.x), u2h(q11.x), f1h)));
        add2h(acc1, __hadd2(lerp2(u2h(q00.y), u2h(q01.y), f0h),
                            lerp2(u2h(q10.y), u2h(q11.y), f1h)));
        add2h(acc2, __hadd2(lerp2(u2h(q00.z), u2h(q01.z), f0h),
                            lerp2(u2h(q10.z), u2h(q11.z), f1h)));
        add2h(acc3, __hadd2(lerp2(u2h(q00.w), u2h(q01.w), f0h),
                            lerp2(u2h(q10.w), u2h(q11.w), f1h)));
    }

    const float2 f0 = unpack2(acc0);
    const float2 f1 = unpack2(acc1);
    const float2 f2 = unpack2(acc2);
    const float2 f3 = unpack2(acc3);
    const float vals[8] = {f0.x, f0.y, f1.x, f1.y, f2.x, f2.y, f3.x, f3.y};

    const float L = -LAMB_;
    const int base = y * NX_ + x;
    #pragma unroll
    for (int e = 0; e < 8; ++e)
        out[(8 * zo + e) * (NY_ * NX_) + base] = L * vals[e];
}

// ---------------------------------------------------------------------------
extern "C" void kernel_launch(void* const* d_in, const int* in_sizes, int n_in,
                              void* d_out, int out_size) {
    const float* x = (const float*)d_in[0];
    const float* p = (const float*)d_in[1];
    if (n_in >= 2 && in_sizes[0] == 786432) {   // defensive swap by size
        const float* tmp = x; x = p; p = tmp;
    }
    float* out = (float*)d_out;

    // Two no-ops keep the ncu capture point (-s 5) on fwd_kernel.
    noop_kernel<<<1, 32>>>();
    noop_kernel<<<1, 32>>>();
    pack_kernel<<<dim3(NX_ / 32, NY_), 256>>>(x);
    fwd_kernel<<<dim3(DET0_ / 32, A_, 2), 128>>>(p);
    bwd_kernel<<<dim3(NX_ / 16, NY_ / 4), 256>>>(out);
}

// round 14
// speedup vs baseline: 1.0591x; 1.0138x over previous
#include <cuda_runtime.h>
#include <cuda_fp16.h>

#define A_    96
#define DET0_ 256
#define T_    256
#define NZ_   32
#define NY_   256
#define NX_   256
#define DTH   0.0327249234748936795f   // pi/96
#define LAMB_ 0.01f

#define RX_   268                      // padded row length in cells
#define OFF_  4                        // zero-pad offset on every side
#define RROW_ 258                      // padded res row (u cells)
#define RES_U4 ((A_ * RROW_ * 32 * 2) / 16)   // res size in uint4 (99072)

// fp16 scratch. Vol pads NEVER written -> stay zero; res fully re-zeroed by
// pack every launch (fwd accumulates into it with atomics).
__device__ __half g_vol_s[RX_ * RX_ * 32];    // [y+OFF][x+OFF][z], 64 B cells
__device__ __half g_res_h[A_ * RROW_ * 32];   // [a][(u+1)][z], 64 B cells

typedef unsigned long long ull;

__device__ __forceinline__ __half2 u2h(unsigned v) {
    return *reinterpret_cast<__half2*>(&v);
}
// acc(f32x2) += cvt_f32x2(h)
__device__ __forceinline__ void add2h(ull& acc, __half2 h) {
    float lo = __low2float(h), hi = __high2float(h);
    ull v; asm("mov.b64 %0, {%1, %2};" : "=l"(v) : "f"(lo), "f"(hi));
    asm("add.rn.f32x2 %0, %0, %1;" : "+l"(acc) : "l"(v));
}
__device__ __forceinline__ float2 unpack2(ull a) {
    float2 r; asm("mov.b64 {%0, %1}, %2;" : "=f"(r.x), "=f"(r.y) : "l"(a)); return r;
}
__device__ __forceinline__ __half2 lerp2(__half2 a, __half2 b, __half2 f) {
    return __hfma2(f, __hsub2(b, a), a);
}

struct S4 { __half2 a, b, c, d; };

// One bilinear sample (8 z as 4 half2), fully fp16 lerp.
__device__ __forceinline__ S4 sample_at(const char* __restrict__ volb,
                                        float tf, float cc, float ss,
                                        float bxx, float byy, int zo) {
    const float ix = fmaf(tf, cc, bxx);
    const float iy = fmaf(tf, ss, byy);
    const float x0f = floorf(ix);
    const float y0f = floorf(iy);
    const float fx = ix - x0f;
    const float fy = iy - y0f;
    const int xi = (int)x0f + OFF_;
    const int yi = (int)y0f + OFF_;

    const char* cell = volb + (yi * RX_ + xi) * 64 + zo * 16;
    const uint4 L0 = *reinterpret_cast<const uint4*>(cell);
    const uint4 R0 = *reinterpret_cast<const uint4*>(cell + 64);
    const uint4 L1 = *reinterpret_cast<const uint4*>(cell + RX_ * 64);
    const uint4 R1 = *reinterpret_cast<const uint4*>(cell + RX_ * 64 + 64);

    const __half2 fxh = __float2half2_rn(fx);
    const __half2 fyh = __float2half2_rn(fy);

    S4 r;
    r.a = lerp2(lerp2(u2h(L0.x), u2h(R0.x), fxh),
                lerp2(u2h(L1.x), u2h(R1.x), fxh), fyh);
    r.b = lerp2(lerp2(u2h(L0.y), u2h(R0.y), fxh),
                lerp2(u2h(L1.y), u2h(R1.y), fxh), fyh);
    r.c = lerp2(lerp2(u2h(L0.z), u2h(R0.z), fxh),
                lerp2(u2h(L1.z), u2h(R1.z), fxh), fyh);
    r.d = lerp2(lerp2(u2h(L0.w), u2h(R0.w), fxh),
                lerp2(u2h(L1.w), u2h(R1.w), fxh), fyh);
    return r;
}

__global__ void noop_kernel() {}

// ---------------------------------------------------------------------------
// Kernel 1: transpose+pack x -> fp16 vol cells, and zero the ENTIRE res
// buffer (2048 blocks x 49 uint4 = 100352 >= 99072).
// ---------------------------------------------------------------------------
__global__ __launch_bounds__(256) void pack_kernel(const float* __restrict__ x) {
    {
        const int flat = blockIdx.y * 8 + blockIdx.x;
        const int idx = flat * 49 + threadIdx.x;
        if (threadIdx.x < 49 && idx < RES_U4)
            reinterpret_cast<uint4*>(g_res_h)[idx] = make_uint4(0u, 0u, 0u, 0u);
    }

    __shared__ float tile[32][33];   // [z][x]
    const int xb = blockIdx.x * 32;
    const int y  = blockIdx.y;
    {
        const int z  = threadIdx.x >> 3;
        const int xq = threadIdx.x & 7;
        float4 v = reinterpret_cast<const float4*>(x + z * (NY_ * NX_) + y * NX_ + xb)[xq];
        tile[z][4 * xq + 0] = v.x;
        tile[z][4 * xq + 1] = v.y;
        tile[z][4 * xq + 2] = v.z;
        tile[z][4 * xq + 3] = v.w;
    }
    __syncthreads();
    const int zo = threadIdx.x & 7;     // z quad: z = 4*zo..4*zo+3
    const int xl = threadIdx.x >> 3;    // 0..31
    __half2 h0 = __floats2half2_rn(tile[4 * zo + 0][xl], tile[4 * zo + 1][xl]);
    __half2 h1 = __floats2half2_rn(tile[4 * zo + 2][xl], tile[4 * zo + 3][xl]);
    uint2 w;
    w.x = *reinterpret_cast<unsigned*>(&h0);
    w.y = *reinterpret_cast<unsigned*>(&h1);
    *reinterpret_cast<uint2*>(reinterpret_cast<char*>(g_vol_s)
        + ((y + OFF_) * RX_ + (xb + xl + OFF_)) * 64 + zo * 8) = w;
}

// ---------------------------------------------------------------------------
// Kernel 2: forward project + residual (unchanged from best). Grid (8, A, 2):
// blockIdx.z = per-ray half (midpoint split). 128 thr: zo = tid&3, ul = tid>>2.
// t-pairs combined fp16, accumulated f32x2. Partials via fp16x2 atomicAdd
// (exactly 2 commutative adds per address -> deterministic).
// ---------------------------------------------------------------------------
__global__ __launch_bounds__(128) void fwd_kernel(const float* __restrict__ p) {
    const int tid = threadIdx.x;
    const int zo  = tid & 3;
    const int ul  = tid >> 2;
    const int a   = blockIdx.y;
    const int u   = blockIdx.x * 32 + ul;
    const int seg = blockIdx.z;

    float s, c;
    sincosf((float)a * DTH, &s, &c);

    const float uc = (float)u - 127.5f;
    const float bxx = fmaf(uc, -s, 127.5f);
    const float byy = fmaf(uc,  c, 127.5f);

    const float xa = (-1.0f - bxx) / c, xb2 = (257.0f - bxx) / c;
    const float ya = (-1.0f - byy) / s, yb2 = (257.0f - byy) / s;
    const float lo = fmaxf(fminf(xa, xb2), fminf(ya, yb2));
    const float hi = fminf(fmaxf(xa, xb2), fmaxf(ya, yb2));
    const int t0g = (int)fminf(fmaxf(lo + 126.0f, 0.0f), 256.0f);
    const int t1g = (int)fminf(fmaxf(hi + 129.0f, -1.0f), 255.0f);
    const int mid = (t0g + t1g + 1) >> 1;
    const int t0 = seg ? mid : t0g;
    const int t1 = seg ? t1g : (mid - 1);

    ull acc0 = 0ull, acc1 = 0ull, acc2 = 0ull, acc3 = 0ull;
    const char* __restrict__ volb = reinterpret_cast<const char*>(g_vol_s);

    const int len = t1 - t0 + 1;
    const int nPairs = (len > 0) ? (len >> 1) : 0;

    float tf = (float)t0 - 127.5f;
    for (int i = 0; i < nPairs; ++i, tf += 2.0f) {
        const S4 sA = sample_at(volb, tf,        c, s, bxx, byy, zo);
        const S4 sB = sample_at(volb, tf + 1.0f, c, s, bxx, byy, zo);
        add2h(acc0, __hadd2(sA.a, sB.a));
        add2h(acc1, __hadd2(sA.b, sB.b));
        add2h(acc2, __hadd2(sA.c, sB.c));
        add2h(acc3, __hadd2(sA.d, sB.d));
    }
    if (len > 0 && (len & 1)) {
        const S4 sA = sample_at(volb, tf, c, s, bxx, byy, zo);
        add2h(acc0, sA.a);
        add2h(acc1, sA.b);
        add2h(acc2, sA.c);
        add2h(acc3, sA.d);
    }

    const float2 f0 = unpack2(acc0);
    const float2 f1 = unpack2(acc1);
    const float2 f2 = unpack2(acc2);
    const float2 f3 = unpack2(acc3);
    float r[8] = {f0.x, f0.y, f1.x, f1.y, f2.x, f2.y, f3.x, f3.y};

    if (seg == 0) {
        #pragma unroll
        for (int e = 0; e < 8; ++e) {
            const int m = (e << 2) | zo;   // z = 8*zo + e
            r[e] -= p[(a * 4 + (m >> 3)) * (8 * 256) + (m & 7) * 256 + u];
        }
    }

    __half2* dst = reinterpret_cast<__half2*>(
        g_res_h + (a * RROW_ + u + 1) * 32 + zo * 8);
    atomicAdd(dst + 0, __floats2half2_rn(r[0], r[1]));
    atomicAdd(dst + 1, __floats2half2_rn(r[2], r[3]));
    atomicAdd(dst + 2, __floats2half2_rn(r[4], r[5]));
    atomicAdd(dst + 3, __floats2half2_rn(r[6], r[7]));
}

// ---------------------------------------------------------------------------
// Kernel 3: back project. 256 thr: zh = tid&1 (z half: 16 z = 8 half2),
// pixel = tid>>1 -> 16x8 tile. Grid (16, 32). Per thread: 16 z x 1 pixel.
// Branchless validity; 4-angle fp16 tree (pair hadd into running fp16 sums,
// quad hadd, then one f32x2 accumulate per 4 angles).
// ---------------------------------------------------------------------------
__global__ __launch_bounds__(256) void bwd_kernel(float* __restrict__ out) {
    __shared__ float2 ang[A_];
    const int tid = threadIdx.x;
    if (tid < A_) {
        float s, c;
        sincosf((float)tid * DTH, &s, &c);
        ang[tid] = make_float2(s, c);
    }
    __syncthreads();

    const int zh    = tid & 1;       // z 0..15 or 16..31
    const int pixel = tid >> 1;      // 0..127
    const int sx    = pixel & 15;
    const int sy    = pixel >> 4;    // 0..7
    const int x = blockIdx.x * 16 + sx;
    const int y = blockIdx.y * 8 + sy;

    const float Xc = (float)x - 127.5f;
    const float Yc = (float)y - 127.5f;

    ull acc[8];
    #pragma unroll
    for (int k = 0; k < 8; ++k) acc[k] = 0ull;

    const char* __restrict__ resb =
        reinterpret_cast<const char*>(g_res_h) + zh * 32;

    #pragma unroll 1
    for (int a = 0; a < A_; a += 4) {
        __half2 s01[8], s23[8];

        #pragma unroll
        for (int q = 0; q < 2; ++q) {
            __half2* sp = q ? s23 : s01;
            #pragma unroll
            for (int e = 0; e < 2; ++e) {
                const int aa = a + 2 * q + e;
                const float2 an = ang[aa];
                const float ub = fmaf(Yc, an.y, fmaf(Xc, -an.x, 127.5f));
                int u0 = __float2int_rd(ub);
                const bool v = (unsigned)(u0 + 1) <= 256u;
                const float fu = v ? (ub - (float)u0) : 0.0f;
                u0 = v ? u0 : -1;   // pad cell (zero), weight 0

                const char* cell = resb + (aa * RROW_ + u0 + 1) * 64;
                const uint4 q0a = *reinterpret_cast<const uint4*>(cell);
                const uint4 q0b = *reinterpret_cast<const uint4*>(cell + 16);
                const uint4 q1a = *reinterpret_cast<const uint4*>(cell + 64);
                const uint4 q1b = *reinterpret_cast<const uint4*>(cell + 80);

                const __half2 fh = __float2half2_rn(fu);
                __half2 l[8];
                l[0] = lerp2(u2h(q0a.x), u2h(q1a.x), fh);
                l[1] = lerp2(u2h(q0a.y), u2h(q1a.y), fh);
                l[2] = lerp2(u2h(q0a.z), u2h(q1a.z), fh);
                l[3] = lerp2(u2h(q0a.w), u2h(q1a.w), fh);
                l[4] = lerp2(u2h(q0b.x), u2h(q1b.x), fh);
                l[5] = lerp2(u2h(q0b.y), u2h(q1b.y), fh);
                l[6] = lerp2(u2h(q0b.z), u2h(q1b.z), fh);
                l[7] = lerp2(u2h(q0b.w), u2h(q1b.w), fh);

                if (e == 0) {
                    #pragma unroll
                    for (int k = 0; k < 8; ++k) sp[k] = l[k];
                } else {
                    #pragma unroll
                    for (int k = 0; k < 8; ++k) sp[k] = __hadd2(sp[k], l[k]);
                }
            }
        }

        #pragma unroll
        for (int k = 0; k < 8; ++k)
            add2h(acc[k], __hadd2(s01[k], s23[k]));
    }

    const float L = -LAMB_;
    const int base = y * NX_ + x;
    #pragma unroll
    for (int k = 0; k < 8; ++k) {
        const float2 f = unpack2(acc[k]);
        out[(16 * zh + 2 * k + 0) * (NY_ * NX_) + base] = L * f.x;
        out[(16 * zh + 2 * k + 1) * (NY_ * NX_) + base] = L * f.y;
    }
}

// ---------------------------------------------------------------------------
extern "C" void kernel_launch(void* const* d_in, const int* in_sizes, int n_in,
                              void* d_out, int out_size) {
    const float* x = (const float*)d_in[0];
    const float* p = (const float*)d_in[1];
    if (n_in >= 2 && in_sizes[0] == 786432) {   // defensive swap by size
        const float* tmp = x; x = p; p = tmp;
    }
    float* out = (float*)d_out;

    // One no-op: ncu capture (-s 5, 2 harness pre-launches) lands on bwd.
    noop_kernel<<<1, 32>>>();
    pack_kernel<<<dim3(NX_ / 32, NY_), 256>>>(x);
    fwd_kernel<<<dim3(DET0_ / 32, A_, 2), 128>>>(p);
    bwd_kernel<<<dim3(NX_ / 16, NY_ / 8), 256>>>(out);
}